// round 1
// baseline (speedup 1.0000x reference)
#include <cuda_runtime.h>
#include <cstdint>

#define B_SZ   8192
#define IN_SZ  2048
#define OUT_SZ 2048
#define G_SZ   5
#define KPACK  6
#define K_SZ   (IN_SZ * KPACK)   // 12288
#define EPS_F  1e-8f

#define BM 128
#define BN 128
#define BK 32
#define STAGES 4
#define LROW 36                  // BK + 4 pad (floats per smem row)
#define KITERS (K_SZ / BK)       // 384

// scratch: packed A [B, K] and packed W [OUT, K], both K-major, TF32-rounded fp32
__device__ float g_Apack[(size_t)B_SZ  * K_SZ];
__device__ float g_Wpack[(size_t)OUT_SZ * K_SZ];

__device__ __forceinline__ float tf32r(float x) {
    uint32_t u;
    asm("cvt.rna.tf32.f32 %0, %1;\n" : "=r"(u) : "f"(x));
    return __uint_as_float(u);
}

// ---------------------------------------------------------------------------
// Pack A: faithful B-spline basis recursion (matches reference exactly in fp32)
// A[b, i*6 + 0] = x[b,i]; A[b, i*6 + 1 + g] = basis[b,i,g]
// ---------------------------------------------------------------------------
__global__ void pack_A_kernel(const float* __restrict__ x,
                              const float* __restrict__ grid) {
    int idx = blockIdx.x * 256 + threadIdx.x;          // b*IN + i
    if (idx >= B_SZ * IN_SZ) return;
    int i = idx & (IN_SZ - 1);
    float xv = x[idx];

    float g[G_SZ];
#pragma unroll
    for (int t = 0; t < G_SZ; t++) g[t] = grid[i * G_SZ + t];

    float diff[G_SZ], bas[G_SZ];
#pragma unroll
    for (int t = 0; t < G_SZ; t++) {
        diff[t] = xv - g[t];
        bas[t] = (diff[t] >= 0.0f && diff[t] < 1.0f) ? 1.0f : 0.0f;
    }

#pragma unroll
    for (int order = 1; order <= 3; order++) {
        float nb[G_SZ];
#pragma unroll
        for (int j = 0; j < G_SZ; j++) nb[j] = bas[j];
#pragma unroll
        for (int j = 0; j < G_SZ; j++) {
            if (j < G_SZ - order) {
                int i2 = (j + order     < G_SZ - 1) ? (j + order)     : (G_SZ - 1);
                int i3 = (j + order + 1 < G_SZ - 1) ? (j + order + 1) : (G_SZ - 1);
                // note: (diff[j] - g[j]) == x - 2*g[j], kept faithfully to reference
                float t1 = (diff[j] - g[j]) / (g[i2] - g[j] + EPS_F) * bas[j];
                float t2 = (g[i3] - diff[j]) / (g[i3] - g[j + 1] + EPS_F) * bas[j + 1];
                nb[j] = t1 + t2;
            }
        }
#pragma unroll
        for (int j = 0; j < G_SZ; j++) bas[j] = nb[j];
    }

    size_t o = (size_t)(idx >> 11) * K_SZ + (size_t)i * KPACK;  // idx/IN_SZ
    g_Apack[o] = tf32r(xv);
#pragma unroll
    for (int t = 0; t < G_SZ; t++) g_Apack[o + 1 + t] = tf32r(bas[t]);
}

// ---------------------------------------------------------------------------
// Pack W: W[o, i*6 + 0] = base_weight[o,i]; W[o, i*6 + 1 + g] = spline_weight[o,i,g]
// ---------------------------------------------------------------------------
__global__ void pack_W_kernel(const float* __restrict__ bw,
                              const float* __restrict__ sw) {
    int idx = blockIdx.x * 256 + threadIdx.x;          // o*IN + i
    if (idx >= OUT_SZ * IN_SZ) return;
    int o = idx >> 11;                                  // idx / IN_SZ
    int i = idx & (IN_SZ - 1);
    size_t dst = (size_t)o * K_SZ + (size_t)i * KPACK;
    g_Wpack[dst] = tf32r(bw[idx]);
#pragma unroll
    for (int t = 0; t < G_SZ; t++)
        g_Wpack[dst + 1 + t] = tf32r(sw[(size_t)idx * G_SZ + t]);
}

// ---------------------------------------------------------------------------
// TF32 GEMM: C[M=8192, N=2048] = A @ W^T + bias
// 128x128x32 tile, 4-stage cp.async pipeline, mma.m16n8k8.tf32
// ---------------------------------------------------------------------------
__device__ __forceinline__ void cp16(uint32_t dst, const void* src) {
    asm volatile("cp.async.cg.shared.global [%0], [%1], 16;\n" :: "r"(dst), "l"(src));
}

__global__ __launch_bounds__(256, 1)
void gemm_kernel(const float* __restrict__ bias, float* __restrict__ out) {
    extern __shared__ float smem[];   // [STAGES][A:128*36 | W:128*36]
    const int tid  = threadIdx.x;
    const int lane = tid & 31;
    const int warp = tid >> 5;
    const int wm   = warp & 1;        // 2 warps along M -> 64 rows each
    const int wn   = warp >> 1;       // 4 warps along N -> 32 cols each
    const int gid  = lane >> 2;
    const int tg   = lane & 3;
    const int bn   = blockIdx.x;
    const int bm   = blockIdx.y;

    const float* Ag = g_Apack + (size_t)bm * BM * K_SZ;
    const float* Wg = g_Wpack + (size_t)bn * BN * K_SZ;

    const uint32_t smem_u32 = (uint32_t)__cvta_generic_to_shared(smem);
    const int lrow = tid >> 3;             // 0..31  (+32 per pass)
    const int lcol = (tid & 7) * 4;        // 0,4,...,28

    // prefetch lambda (macro-style)
#define PREFETCH(KT, ST)                                                          \
    {                                                                             \
        uint32_t aBase = smem_u32 + (uint32_t)((ST) * 2 * (BM * LROW)) * 4u;      \
        uint32_t wBase = aBase + (uint32_t)(BM * LROW) * 4u;                      \
        _Pragma("unroll")                                                         \
        for (int p = 0; p < 4; p++) {                                             \
            int r = lrow + p * 32;                                                \
            cp16(aBase + (uint32_t)(r * LROW + lcol) * 4u,                        \
                 Ag + (size_t)r * K_SZ + (KT) * BK + lcol);                       \
            cp16(wBase + (uint32_t)(r * LROW + lcol) * 4u,                        \
                 Wg + (size_t)r * K_SZ + (KT) * BK + lcol);                       \
        }                                                                         \
    }

    float acc[4][4][4];
#pragma unroll
    for (int a = 0; a < 4; a++)
#pragma unroll
        for (int b = 0; b < 4; b++)
#pragma unroll
            for (int c = 0; c < 4; c++) acc[a][b][c] = 0.0f;

#pragma unroll
    for (int s = 0; s < STAGES - 1; s++) {
        PREFETCH(s, s);
        asm volatile("cp.async.commit_group;\n" ::: "memory");
    }

    for (int kt = 0; kt < KITERS; kt++) {
        asm volatile("cp.async.wait_group %0;\n" :: "n"(STAGES - 2) : "memory");
        __syncthreads();

        int pf = kt + STAGES - 1;
        if (pf < KITERS) { PREFETCH(pf, pf & (STAGES - 1)); }
        asm volatile("cp.async.commit_group;\n" ::: "memory");

        const float* As_ = smem + (size_t)(kt & (STAGES - 1)) * 2 * (BM * LROW);
        const float* Ws_ = As_ + BM * LROW;

#pragma unroll
        for (int ks = 0; ks < 4; ks++) {
            const int ko = ks * 8;
            uint32_t a[4][4], b[4][2];
#pragma unroll
            for (int mf = 0; mf < 4; mf++) {
                int r = wm * 64 + mf * 16 + gid;
                a[mf][0] = __float_as_uint(As_[r * LROW + ko + tg]);
                a[mf][1] = __float_as_uint(As_[(r + 8) * LROW + ko + tg]);
                a[mf][2] = __float_as_uint(As_[r * LROW + ko + tg + 4]);
                a[mf][3] = __float_as_uint(As_[(r + 8) * LROW + ko + tg + 4]);
            }
#pragma unroll
            for (int nf = 0; nf < 4; nf++) {
                int cn = wn * 32 + nf * 8 + gid;
                b[nf][0] = __float_as_uint(Ws_[cn * LROW + ko + tg]);
                b[nf][1] = __float_as_uint(Ws_[cn * LROW + ko + tg + 4]);
            }
#pragma unroll
            for (int mf = 0; mf < 4; mf++)
#pragma unroll
                for (int nf = 0; nf < 4; nf++) {
                    asm volatile(
                        "mma.sync.aligned.m16n8k8.row.col.f32.tf32.tf32.f32 "
                        "{%0,%1,%2,%3}, {%4,%5,%6,%7}, {%8,%9}, {%0,%1,%2,%3};\n"
                        : "+f"(acc[mf][nf][0]), "+f"(acc[mf][nf][1]),
                          "+f"(acc[mf][nf][2]), "+f"(acc[mf][nf][3])
                        : "r"(a[mf][0]), "r"(a[mf][1]), "r"(a[mf][2]), "r"(a[mf][3]),
                          "r"(b[nf][0]), "r"(b[nf][1]));
                }
        }
    }

    // epilogue: add bias, store float2
#pragma unroll
    for (int mf = 0; mf < 4; mf++) {
#pragma unroll
        for (int nf = 0; nf < 4; nf++) {
            int row = bm * BM + wm * 64 + mf * 16 + gid;
            int col = bn * BN + wn * 32 + nf * 8 + tg * 2;
            float b0 = bias[col], b1 = bias[col + 1];
            float2 v0 = make_float2(acc[mf][nf][0] + b0, acc[mf][nf][1] + b1);
            float2 v1 = make_float2(acc[mf][nf][2] + b0, acc[mf][nf][3] + b1);
            *(float2*)(out + (size_t)row * OUT_SZ + col) = v0;
            *(float2*)(out + (size_t)(row + 8) * OUT_SZ + col) = v1;
        }
    }
#undef PREFETCH
}

// ---------------------------------------------------------------------------
extern "C" void kernel_launch(void* const* d_in, const int* in_sizes, int n_in,
                              void* d_out, int out_size) {
    const float* x    = (const float*)d_in[0];   // [B, IN]
    const float* bw   = (const float*)d_in[1];   // [OUT, IN]
    const float* bb   = (const float*)d_in[2];   // [OUT]
    const float* sw   = (const float*)d_in[3];   // [OUT, IN, G]
    const float* grid = (const float*)d_in[4];   // [IN, G]
    float* out = (float*)d_out;                  // [B, OUT]

    pack_A_kernel<<<(B_SZ * IN_SZ + 255) / 256, 256>>>(x, grid);
    pack_W_kernel<<<(OUT_SZ * IN_SZ + 255) / 256, 256>>>(bw, sw);

    const int smem_bytes = STAGES * 2 * (BM * LROW) * 4;   // 147456
    cudaFuncSetAttribute(gemm_kernel,
                         cudaFuncAttributeMaxDynamicSharedMemorySize, smem_bytes);
    dim3 g(OUT_SZ / BN, B_SZ / BM);   // (16, 64)
    gemm_kernel<<<g, 256, smem_bytes>>>(bb, out);
}

// round 4
// speedup vs baseline: 1.1568x; 1.1568x over previous
#include <cuda_runtime.h>
#include <cstdint>

#define B_SZ   8192
#define IN_SZ  2048
#define OUT_SZ 2048
#define G_SZ   5
#define KPACK  6
#define K_SZ   (IN_SZ * KPACK)   // 12288
#define EPS_F  1e-8f

// GEMM tiling: 256x128 CTA tile, BK=32 tf32 (128B rows), 8 warps (4m x 2n), warp tile 64x64
#define BM 256
#define BN 128
#define BK 32
#define KITERS (K_SZ / BK)        // 384
#define NSTAGE 4
#define A_STAGE_BYTES (BM * 128)  // 32 KB
#define B_STAGE_BYTES (BN * 128)  // 16 KB
#define STAGE_BYTES (A_STAGE_BYTES + B_STAGE_BYTES)   // 48 KB
#define KROW_BYTES (K_SZ * 4)     // 49152 bytes per packed row

// scratch: packed TF32 A [B, K] and W [OUT, K], k-permuted within 8-float groups
__device__ __align__(128) float g_Apack[(size_t)B_SZ  * K_SZ];
__device__ __align__(128) float g_Wpack[(size_t)OUT_SZ * K_SZ];

__device__ __forceinline__ float tf32r(float x) {
    uint32_t u;
    asm("cvt.rna.tf32.f32 %0, %1;\n" : "=r"(u) : "f"(x));
    return __uint_as_float(u);
}

// permutation within each 8-element k-group: original k -> slot
// k<4 -> 2k ; k>=4 -> 2(k-4)+1   => thread tg's 8B at offset tg*8 holds {k=tg, k=tg+4}
__device__ __forceinline__ int permpos_f(int k) {
    int grp = k >> 3, w = k & 7;
    int q = (w < 4) ? (2 * w) : (2 * (w - 4) + 1);
    return grp * 8 + q;
}

// ---------------------------------------------------------------------------
// faithful B-spline recursion (fp32, matches reference)
// ---------------------------------------------------------------------------
__device__ __forceinline__ void basis5(float xv, const float* g, float* bas) {
    float diff[G_SZ];
#pragma unroll
    for (int t = 0; t < G_SZ; t++) {
        diff[t] = xv - g[t];
        bas[t] = (diff[t] >= 0.0f && diff[t] < 1.0f) ? 1.0f : 0.0f;
    }
#pragma unroll
    for (int order = 1; order <= 3; order++) {
        float nb[G_SZ];
#pragma unroll
        for (int j = 0; j < G_SZ; j++) nb[j] = bas[j];
#pragma unroll
        for (int j = 0; j < G_SZ; j++) {
            if (j < G_SZ - order) {
                int i2 = (j + order     < G_SZ - 1) ? (j + order)     : (G_SZ - 1);
                int i3 = (j + order + 1 < G_SZ - 1) ? (j + order + 1) : (G_SZ - 1);
                float t1 = (diff[j] - g[j]) / (g[i2] - g[j] + EPS_F) * bas[j];
                float t2 = (g[i3] - diff[j]) / (g[i3] - g[j + 1] + EPS_F) * bas[j + 1];
                nb[j] = t1 + t2;
            }
        }
#pragma unroll
        for (int j = 0; j < G_SZ; j++) bas[j] = nb[j];
    }
}

__global__ void pack_A_kernel(const float* __restrict__ x,
                              const float* __restrict__ grid) {
    int idx = blockIdx.x * 256 + threadIdx.x;          // b*IN + i
    if (idx >= B_SZ * IN_SZ) return;
    int i = idx & (IN_SZ - 1);
    int b = idx >> 11;
    float xv = x[idx];
    float g[G_SZ];
#pragma unroll
    for (int t = 0; t < G_SZ; t++) g[t] = grid[i * G_SZ + t];
    float bas[G_SZ];
    basis5(xv, g, bas);

    float* row = g_Apack + (size_t)b * K_SZ;
    int k0 = i * KPACK;
    row[permpos_f(k0)] = tf32r(xv);
#pragma unroll
    for (int t = 0; t < G_SZ; t++)
        row[permpos_f(k0 + 1 + t)] = tf32r(bas[t]);
}

__global__ void pack_W_kernel(const float* __restrict__ bw,
                              const float* __restrict__ sw) {
    int idx = blockIdx.x * 256 + threadIdx.x;          // o*IN + i
    if (idx >= OUT_SZ * IN_SZ) return;
    int o = idx >> 11;
    int i = idx & (IN_SZ - 1);
    float* row = g_Wpack + (size_t)o * K_SZ;
    int k0 = i * KPACK;
    row[permpos_f(k0)] = tf32r(bw[idx]);
#pragma unroll
    for (int t = 0; t < G_SZ; t++)
        row[permpos_f(k0 + 1 + t)] = tf32r(sw[(size_t)idx * G_SZ + t]);
}

// ---------------------------------------------------------------------------
__device__ __forceinline__ uint32_t smem_addr_u32(const void* p) {
    uint32_t a;
    asm("{ .reg .u64 t; cvta.to.shared.u64 t, %1; cvt.u32.u64 %0, t; }"
        : "=r"(a) : "l"(p));
    return a;
}
__device__ __forceinline__ void cpa16(uint32_t dst, const void* src) {
    asm volatile("cp.async.cg.shared.global [%0], [%1], 16;\n" :: "r"(dst), "l"(src));
}
__device__ __forceinline__ void lds64(uint32_t& r0, uint32_t& r1, uint32_t addr) {
    asm volatile("ld.shared.v2.u32 {%0,%1}, [%2];" : "=r"(r0), "=r"(r1) : "r"(addr));
}

// ---------------------------------------------------------------------------
// TF32 GEMM: C[8192,2048] = A @ W^T + bias
// ---------------------------------------------------------------------------
__global__ __launch_bounds__(256, 1)
void gemm_tf32_kernel(const float* __restrict__ bias, float* __restrict__ out) {
    extern __shared__ char smem[];
    const uint32_t sb = smem_addr_u32(smem);
    const int tid = threadIdx.x;
    const int warp = tid >> 5, lane = tid & 31;
    const int gid = lane >> 2, tg = lane & 3;
    const int wm = warp >> 1, wn = warp & 1;   // 4 m-warps x 2 n-warps
    const int bn = blockIdx.x, bm = blockIdx.y;

    const char* Ag = (const char*)(g_Apack + (size_t)(bm * BM) * K_SZ);
    const char* Wg = (const char*)(g_Wpack + (size_t)(bn * BN) * K_SZ);

#define LOADST(KT, ST)                                                           \
    {                                                                            \
        uint32_t base_ = sb + (uint32_t)(ST) * STAGE_BYTES;                      \
        _Pragma("unroll")                                                        \
        for (int p_ = 0; p_ < 8; p_++) {                                         \
            int id_ = tid + p_ * 256;                                            \
            int r_ = id_ >> 3, c_ = id_ & 7;                                     \
            cpa16(base_ + (uint32_t)(r_ * 128 + ((c_ * 16) ^ ((r_ & 3) << 5))),  \
                  Ag + (size_t)r_ * KROW_BYTES + (size_t)(KT) * 128 + c_ * 16);  \
        }                                                                        \
        _Pragma("unroll")                                                        \
        for (int p_ = 0; p_ < 4; p_++) {                                         \
            int id_ = tid + p_ * 256;                                            \
            int r_ = id_ >> 3, c_ = id_ & 7;                                     \
            cpa16(base_ + A_STAGE_BYTES +                                        \
                      (uint32_t)(r_ * 128 + ((c_ * 16) ^ ((r_ & 3) << 5))),      \
                  Wg + (size_t)r_ * KROW_BYTES + (size_t)(KT) * 128 + c_ * 16);  \
        }                                                                        \
        asm volatile("cp.async.commit_group;\n" ::: "memory");                   \
    }

    float acc[4][8][4];
#pragma unroll
    for (int a = 0; a < 4; a++)
#pragma unroll
        for (int b = 0; b < 8; b++)
#pragma unroll
            for (int c = 0; c < 4; c++) acc[a][b][c] = 0.0f;

#pragma unroll
    for (int s = 0; s < NSTAGE - 1; s++) LOADST(s, s);

    for (int kt = 0; kt < KITERS; kt++) {
        asm volatile("cp.async.wait_group %0;\n" :: "n"(NSTAGE - 2) : "memory");
        __syncthreads();

        if (kt + NSTAGE - 1 < KITERS) { LOADST(kt + NSTAGE - 1, (kt + NSTAGE - 1) & (NSTAGE - 1)); }
        else { asm volatile("cp.async.commit_group;\n" ::: "memory"); }

        const uint32_t As = sb + (uint32_t)(kt & (NSTAGE - 1)) * STAGE_BYTES;
        const uint32_t Bs = As + A_STAGE_BYTES;

#pragma unroll
        for (int ks = 0; ks < 4; ks++) {               // 4 k-steps of 8 within BK=32
            const uint32_t koff = (uint32_t)(ks * 32 + tg * 8);
            uint32_t br[8][2];
#pragma unroll
            for (int nf = 0; nf < 8; nf++) {
                int n = wn * 64 + nf * 8 + gid;
                lds64(br[nf][0], br[nf][1],
                      Bs + (uint32_t)(n * 128) + (koff ^ ((uint32_t)(n & 3) << 5)));
            }
#pragma unroll
            for (int mf = 0; mf < 4; mf++) {
                int r = wm * 64 + mf * 16 + gid;
                uint32_t a0, a1, a2, a3;
                uint32_t sw = koff ^ ((uint32_t)(r & 3) << 5);   // (r+8)&3 == r&3
                lds64(a0, a2, As + (uint32_t)(r * 128) + sw);
                lds64(a1, a3, As + (uint32_t)((r + 8) * 128) + sw);
#pragma unroll
                for (int nf = 0; nf < 8; nf++) {
                    asm volatile(
                        "mma.sync.aligned.m16n8k8.row.col.f32.tf32.tf32.f32 "
                        "{%0,%1,%2,%3}, {%4,%5,%6,%7}, {%8,%9}, {%0,%1,%2,%3};\n"
                        : "+f"(acc[mf][nf][0]), "+f"(acc[mf][nf][1]),
                          "+f"(acc[mf][nf][2]), "+f"(acc[mf][nf][3])
                        : "r"(a0), "r"(a1), "r"(a2), "r"(a3),
                          "r"(br[nf][0]), "r"(br[nf][1]));
                }
            }
        }
    }

    // epilogue: bias + float2 stores
#pragma unroll
    for (int mf = 0; mf < 4; mf++) {
        int row = bm * BM + wm * 64 + mf * 16 + gid;
#pragma unroll
        for (int nf = 0; nf < 8; nf++) {
            int col = bn * BN + wn * 64 + nf * 8 + tg * 2;
            float b0 = bias[col], b1 = bias[col + 1];
            float2 v0 = make_float2(acc[mf][nf][0] + b0, acc[mf][nf][1] + b1);
            float2 v1 = make_float2(acc[mf][nf][2] + b0, acc[mf][nf][3] + b1);
            *(float2*)(out + (size_t)row * OUT_SZ + col) = v0;
            *(float2*)(out + (size_t)(row + 8) * OUT_SZ + col) = v1;
        }
    }
#undef LOADST
}

// ---------------------------------------------------------------------------
extern "C" void kernel_launch(void* const* d_in, const int* in_sizes, int n_in,
                              void* d_out, int out_size) {
    const float* x    = (const float*)d_in[0];   // [B, IN]
    const float* bw   = (const float*)d_in[1];   // [OUT, IN]
    const float* bb   = (const float*)d_in[2];   // [OUT]
    const float* sw   = (const float*)d_in[3];   // [OUT, IN, G]
    const float* grid = (const float*)d_in[4];   // [IN, G]
    float* out = (float*)d_out;                  // [B, OUT]

    pack_A_kernel<<<(B_SZ * IN_SZ + 255) / 256, 256>>>(x, grid);
    pack_W_kernel<<<(OUT_SZ * IN_SZ + 255) / 256, 256>>>(bw, sw);

    const int smem_bytes = NSTAGE * STAGE_BYTES;   // 192 KB
    cudaFuncSetAttribute(gemm_tf32_kernel,
                         cudaFuncAttributeMaxDynamicSharedMemorySize, smem_bytes);
    dim3 g(OUT_SZ / BN, B_SZ / BM);   // (16, 32) = 512 CTAs
    gemm_tf32_kernel<<<g, 256, smem_bytes>>>(bb, out);
}

// round 5
// speedup vs baseline: 1.2096x; 1.0456x over previous
#include <cuda_runtime.h>
#include <cstdint>

#define B_SZ   8192
#define IN_SZ  2048
#define OUT_SZ 2048
#define G_SZ   5
#define KPACK  6
#define K_SZ   (IN_SZ * KPACK)   // 12288
#define EPS_F  1e-8f

#define BM 256
#define BN 128
#define BK 32
#define KITERS (K_SZ / BK)        // 384
#define NSTAGE 4
#define A_STAGE_BYTES (16 * 4 * 512)   // 16 panels x 4 kgroups x 512B = 32 KB
#define B_STAGE_BYTES (16 * 2 * 512)   // 16 panels x 2 kgpairs x 512B = 16 KB
#define STAGE_BYTES (A_STAGE_BYTES + B_STAGE_BYTES)   // 48 KB

#define NKG   (K_SZ / 8)          // 1536 k-groups (A)
#define NKGP  (K_SZ / 16)         // 768 kgroup-pairs (B)

// A: [b_panel16][kgroup][512B]; B: [n_panel8][kgpair][512B]  (fragment-blocked)
__device__ __align__(128) float g_Apack[(size_t)B_SZ  * K_SZ];
__device__ __align__(128) float g_Wpack[(size_t)OUT_SZ * K_SZ];

__device__ __forceinline__ float tf32r(float x) {
    uint32_t u;
    asm("cvt.rna.tf32.f32 %0, %1;\n" : "=r"(u) : "f"(x));
    return __uint_as_float(u);
}

// ---------------------------------------------------------------------------
// faithful B-spline recursion (fp32, matches reference)
// ---------------------------------------------------------------------------
__device__ __forceinline__ void basis5(float xv, const float* g, float* bas) {
    float diff[G_SZ];
#pragma unroll
    for (int t = 0; t < G_SZ; t++) {
        diff[t] = xv - g[t];
        bas[t] = (diff[t] >= 0.0f && diff[t] < 1.0f) ? 1.0f : 0.0f;
    }
#pragma unroll
    for (int order = 1; order <= 3; order++) {
        float nb[G_SZ];
#pragma unroll
        for (int j = 0; j < G_SZ; j++) nb[j] = bas[j];
#pragma unroll
        for (int j = 0; j < G_SZ; j++) {
            if (j < G_SZ - order) {
                int i2 = (j + order     < G_SZ - 1) ? (j + order)     : (G_SZ - 1);
                int i3 = (j + order + 1 < G_SZ - 1) ? (j + order + 1) : (G_SZ - 1);
                float t1 = (diff[j] - g[j]) / (g[i2] - g[j] + EPS_F) * bas[j];
                float t2 = (g[i3] - diff[j]) / (g[i3] - g[j + 1] + EPS_F) * bas[j + 1];
                nb[j] = t1 + t2;
            }
        }
#pragma unroll
        for (int j = 0; j < G_SZ; j++) bas[j] = nb[j];
    }
}

// ---------------------------------------------------------------------------
// pack_A: tile 16 b x 128 i per block; stage in smem in exact gmem image,
// then coalesced float4 writes (48KB contiguous per block).
// A fragment block: within (panel, kgroup): chunk=( (b&7)*4 + (k&3) ),
// float pos = ((b>>3)&1) + 2*((k>>2)&1)
// ---------------------------------------------------------------------------
__global__ __launch_bounds__(256, 4)
void pack_A_kernel(const float* __restrict__ x, const float* __restrict__ grid) {
    extern __shared__ float s[];
    float* sOut  = s;            // 12288 floats (48KB)
    float* sGrid = s + 12288;    // 640 floats
    const int tid = threadIdx.x;
    const int b0 = blockIdx.x * 16, i0 = blockIdx.y * 128;

    for (int t = tid; t < 128 * G_SZ; t += 256)
        sGrid[t] = grid[(size_t)i0 * G_SZ + t];
    __syncthreads();

    const int bl0 = tid >> 5;           // 0..7 (+8)
    const int il0 = tid & 31;           // 0..31 (+32,64,96)
#pragma unroll
    for (int pb = 0; pb < 2; pb++) {
        int bl = bl0 + pb * 8;
#pragma unroll
        for (int pi = 0; pi < 4; pi++) {
            int il = il0 + pi * 32;
            float xv = x[(size_t)(b0 + bl) * IN_SZ + i0 + il];
            float g[G_SZ];
#pragma unroll
            for (int t = 0; t < G_SZ; t++) g[t] = sGrid[il * G_SZ + t];
            float bas[G_SZ], v[KPACK];
            basis5(xv, g, bas);
            v[0] = tf32r(xv);
#pragma unroll
            for (int t = 0; t < G_SZ; t++) v[1 + t] = tf32r(bas[t]);
#pragma unroll
            for (int c = 0; c < KPACK; c++) {
                int kr = il * KPACK + c;           // k rel to block (i0*6 is mult of 8)
                int kgl = kr >> 3;
                int chunk = ((bl & 7) << 2) + (kr & 3);
                int pos = ((bl >> 3) & 1) + (((kr >> 2) & 1) << 1);
                sOut[kgl * 128 + chunk * 4 + pos] = v[c];
            }
        }
    }
    __syncthreads();

    // block output = panels (b0/16) kgroups [i0*6/8, +96) : 48KB contiguous
    float4* dst = (float4*)g_Apack +
                  ((size_t)(b0 >> 4) * NKG + (size_t)(i0 * KPACK) / 8) * 32;
    const float4* srcv = (const float4*)sOut;
#pragma unroll
    for (int j = 0; j < 12; j++) dst[tid + j * 256] = srcv[tid + j * 256];
}

// ---------------------------------------------------------------------------
// pack_W: tile 8 o x 256 i per block.
// B fragment block: within (panel, kgpair): chunk=( (o&7)*4 + (k&3) ), pos=(k&15)>>2
// ---------------------------------------------------------------------------
__global__ __launch_bounds__(256, 4)
void pack_W_kernel(const float* __restrict__ bw, const float* __restrict__ sw) {
    extern __shared__ float s[];
    float* sOut = s;             // 12288 floats
    const int tid = threadIdx.x;
    const int o0 = blockIdx.x * 8, i0 = blockIdx.y * 256;

    const int ol = tid >> 5;            // 0..7
    const int il0 = tid & 31;           // +32 x8
#pragma unroll
    for (int pi = 0; pi < 8; pi++) {
        int il = il0 + pi * 32;
        size_t oi = (size_t)(o0 + ol) * IN_SZ + i0 + il;
        float v[KPACK];
        v[0] = tf32r(bw[oi]);
#pragma unroll
        for (int t = 0; t < G_SZ; t++) v[1 + t] = tf32r(sw[oi * G_SZ + t]);
#pragma unroll
        for (int c = 0; c < KPACK; c++) {
            int kr = il * KPACK + c;               // i0*6 is mult of 16
            int pl = kr >> 4;
            int chunk = ((ol & 7) << 2) + (kr & 3);
            int pos = (kr & 15) >> 2;
            sOut[pl * 128 + chunk * 4 + pos] = v[c];
        }
    }
    __syncthreads();

    float4* dst = (float4*)g_Wpack +
                  ((size_t)(o0 >> 3) * NKGP + (size_t)(i0 * KPACK) / 16) * 32;
    const float4* srcv = (const float4*)sOut;
#pragma unroll
    for (int j = 0; j < 12; j++) dst[tid + j * 256] = srcv[tid + j * 256];
}

// ---------------------------------------------------------------------------
__device__ __forceinline__ uint32_t smem_addr_u32(const void* p) {
    uint32_t a;
    asm("{ .reg .u64 t; cvta.to.shared.u64 t, %1; cvt.u32.u64 %0, t; }"
        : "=r"(a) : "l"(p));
    return a;
}
__device__ __forceinline__ void cpa16(uint32_t dst, const void* src) {
    asm volatile("cp.async.cg.shared.global [%0], [%1], 16;\n" :: "r"(dst), "l"(src));
}
__device__ __forceinline__ void lds128(uint32_t& r0, uint32_t& r1,
                                       uint32_t& r2, uint32_t& r3, uint32_t addr) {
    asm volatile("ld.shared.v4.u32 {%0,%1,%2,%3}, [%4];"
                 : "=r"(r0), "=r"(r1), "=r"(r2), "=r"(r3) : "r"(addr));
}

// ---------------------------------------------------------------------------
// TF32 GEMM: C[8192,2048] = A @ W^T + bias.  256x128 CTA, 8 warps (4m x 2n),
// warp tile 64x64. All fragments are single lds128 at panel_base + lane*16.
// ---------------------------------------------------------------------------
__global__ __launch_bounds__(256, 1)
void gemm_tf32_kernel(const float* __restrict__ bias, float* __restrict__ out) {
    extern __shared__ char smem[];
    const uint32_t sb = smem_addr_u32(smem);
    const int tid = threadIdx.x;
    const int warp = tid >> 5, lane = tid & 31;
    const int gid = lane >> 2, tg = lane & 3;
    const int wm = warp >> 1, wn = warp & 1;     // 4 m-warps x 2 n-warps
    const int bn = blockIdx.x, bm = blockIdx.y;

    const char* Ag = (const char*)g_Apack + (size_t)(bm * 16) * NKG * 512;
    const char* Wg = (const char*)g_Wpack + (size_t)(bn * 16) * NKGP * 512;
    const uint32_t lane16 = (uint32_t)lane * 16u;

#define LOADST(KT, ST)                                                             \
    {                                                                              \
        uint32_t base_ = sb + (uint32_t)(ST) * STAGE_BYTES;                        \
        _Pragma("unroll")                                                          \
        for (int p_ = 0; p_ < 8; p_++) {   /* A: 2048 chunks */                    \
            int id_ = tid + p_ * 256;                                              \
            int pan_ = id_ >> 7, kgl_ = (id_ >> 5) & 3, ch_ = id_ & 31;            \
            cpa16(base_ + (uint32_t)(pan_ * 2048 + kgl_ * 512 + ch_ * 16),         \
                  Ag + ((size_t)pan_ * NKG + (size_t)(KT) * 4 + kgl_) * 512        \
                     + ch_ * 16);                                                  \
        }                                                                          \
        _Pragma("unroll")                                                          \
        for (int p_ = 0; p_ < 4; p_++) {   /* B: 1024 chunks */                    \
            int id_ = tid + p_ * 256;                                              \
            int pan_ = id_ >> 6, pl_ = (id_ >> 5) & 1, ch_ = id_ & 31;             \
            cpa16(base_ + A_STAGE_BYTES +                                          \
                      (uint32_t)(pan_ * 1024 + pl_ * 512 + ch_ * 16),              \
                  Wg + ((size_t)pan_ * NKGP + (size_t)(KT) * 2 + pl_) * 512        \
                     + ch_ * 16);                                                  \
        }                                                                          \
        asm volatile("cp.async.commit_group;\n" ::: "memory");                     \
    }

    float acc[4][8][4];
#pragma unroll
    for (int a = 0; a < 4; a++)
#pragma unroll
        for (int b = 0; b < 8; b++)
#pragma unroll
            for (int c = 0; c < 4; c++) acc[a][b][c] = 0.0f;

#pragma unroll
    for (int s = 0; s < NSTAGE - 1; s++) LOADST(s, s);

    for (int kt = 0; kt < KITERS; kt++) {
        asm volatile("cp.async.wait_group %0;\n" :: "n"(NSTAGE - 2) : "memory");
        __syncthreads();

        if (kt + NSTAGE - 1 < KITERS) { LOADST(kt + NSTAGE - 1, (kt + NSTAGE - 1) & (NSTAGE - 1)); }
        else { asm volatile("cp.async.commit_group;\n" ::: "memory"); }

        const uint32_t As = sb + (uint32_t)(kt & (NSTAGE - 1)) * STAGE_BYTES;
        const uint32_t Bs = As + A_STAGE_BYTES;

        uint32_t bp[8][4];   // B fragments for a ks-pair: [nf][ks&1 selects half]
#pragma unroll
        for (int ks = 0; ks < 4; ks++) {
            if ((ks & 1) == 0) {
#pragma unroll
                for (int nf = 0; nf < 8; nf++) {
                    uint32_t baddr = Bs + (uint32_t)(((wn * 8 + nf) * 2 + (ks >> 1)) * 512)
                                        + lane16;
                    lds128(bp[nf][0], bp[nf][1], bp[nf][2], bp[nf][3], baddr);
                }
            }
            const int h = (ks & 1) * 2;
#pragma unroll
            for (int mf = 0; mf < 4; mf++) {
                uint32_t a0, a1, a2, a3;
                uint32_t aaddr = As + (uint32_t)(((wm * 4 + mf) * 4 + ks) * 512) + lane16;
                lds128(a0, a1, a2, a3, aaddr);
#pragma unroll
                for (int nf = 0; nf < 8; nf++) {
                    asm volatile(
                        "mma.sync.aligned.m16n8k8.row.col.f32.tf32.tf32.f32 "
                        "{%0,%1,%2,%3}, {%4,%5,%6,%7}, {%8,%9}, {%0,%1,%2,%3};\n"
                        : "+f"(acc[mf][nf][0]), "+f"(acc[mf][nf][1]),
                          "+f"(acc[mf][nf][2]), "+f"(acc[mf][nf][3])
                        : "r"(a0), "r"(a1), "r"(a2), "r"(a3),
                          "r"(bp[nf][h]), "r"(bp[nf][h + 1]));
                }
            }
        }
    }

    // epilogue: bias + float2 stores
#pragma unroll
    for (int mf = 0; mf < 4; mf++) {
        int row = bm * BM + wm * 64 + mf * 16 + gid;
#pragma unroll
        for (int nf = 0; nf < 8; nf++) {
            int col = bn * BN + wn * 64 + nf * 8 + tg * 2;
            float b0 = bias[col], b1 = bias[col + 1];
            float2 v0 = make_float2(acc[mf][nf][0] + b0, acc[mf][nf][1] + b1);
            float2 v1 = make_float2(acc[mf][nf][2] + b0, acc[mf][nf][3] + b1);
            *(float2*)(out + (size_t)row * OUT_SZ + col) = v0;
            *(float2*)(out + (size_t)(row + 8) * OUT_SZ + col) = v1;
        }
    }
#undef LOADST
}

// ---------------------------------------------------------------------------
extern "C" void kernel_launch(void* const* d_in, const int* in_sizes, int n_in,
                              void* d_out, int out_size) {
    const float* x    = (const float*)d_in[0];   // [B, IN]
    const float* bw   = (const float*)d_in[1];   // [OUT, IN]
    const float* bb   = (const float*)d_in[2];   // [OUT]
    const float* sw   = (const float*)d_in[3];   // [OUT, IN, G]
    const float* grid = (const float*)d_in[4];   // [IN, G]
    float* out = (float*)d_out;                  // [B, OUT]

    const int packA_smem = (12288 + 640) * 4;
    const int packW_smem = 12288 * 4;
    cudaFuncSetAttribute(pack_A_kernel,
                         cudaFuncAttributeMaxDynamicSharedMemorySize, packA_smem);
    cudaFuncSetAttribute(pack_W_kernel,
                         cudaFuncAttributeMaxDynamicSharedMemorySize, packW_smem);

    pack_A_kernel<<<dim3(B_SZ / 16, IN_SZ / 128), 256, packA_smem>>>(x, grid);
    pack_W_kernel<<<dim3(OUT_SZ / 8, IN_SZ / 256), 256, packW_smem>>>(bw, sw);

    const int smem_bytes = NSTAGE * STAGE_BYTES;   // 192 KB
    cudaFuncSetAttribute(gemm_tf32_kernel,
                         cudaFuncAttributeMaxDynamicSharedMemorySize, smem_bytes);
    dim3 g(OUT_SZ / BN, B_SZ / BM);   // (16, 32) = 512 CTAs
    gemm_tf32_kernel<<<g, 256, smem_bytes>>>(bb, out);
}